// round 5
// baseline (speedup 1.0000x reference)
#include <cuda_runtime.h>
#include <cuda_bf16.h>
#include <cstdint>

// Embedding gather + sinusoidal positional encoding.
// out[row, c] = W[ids[row], c] + (row even ? sin : cos)(row * freq(c)),
//   freq(c) = 10000^(-2c/D)
//
// D = 1024, TOKENS = 8192.
// Persistent-style grid (NBLK CTAs); each CTA owns all 1024 columns (thread t
// -> cols 4t..4t+3) and strides over even/odd row PAIRS with stride 2*NBLK.
// The trig prologue (start/delta/jump rotors, accurate sincosf) runs ONCE per
// thread; each row is then 4 FMA/column via rotor rotation. This removes the
// per-CTA trig recomputation that dominated issue in the previous version.

static constexpr int D       = 1024;
static constexpr int VEC     = 4;
static constexpr int THREADS = D / VEC;   // 256
static constexpr int NBLK    = 592;       // 4 CTAs/SM on 148 SMs

__global__ __launch_bounds__(THREADS, 5)
void emb_pe_kernel(const int* __restrict__ ids,
                   const float* __restrict__ W,
                   float* __restrict__ out,
                   int rows)
{
    const int t  = threadIdx.x;            // 0..255
    const int c0 = t * VEC;

    // freq(c) = 2^(kexp * c),  kexp = -2*log2(10000)/D
    const float kexp = -13.287712379549449f * 2.0f / (float)D;

    const int row_start = 2 * blockIdx.x;       // even
    const int stride    = 2 * NBLK;             // row-pair stride

    // Rotors (computed once per thread):
    //  (s,c)   : current angle = row * freq
    //  (sd,cd) : +1 row
    //  (sj,cj) : +(stride-1) rows (jump from odd row of this pair to even row
    //            of this CTA's next pair)
    float s[VEC], c[VEC], sd[VEC], cd[VEC], sj[VEC], cj[VEC];
#pragma unroll
    for (int i = 0; i < VEC; i++) {
        float freq = exp2f(kexp * (float)(c0 + i));
        sincosf((float)row_start * freq, &s[i], &c[i]);
        sincosf(freq, &sd[i], &cd[i]);
        sincosf((float)(stride - 1) * freq, &sj[i], &cj[i]);
    }

    const float* Wc = W + c0;

    for (int row = row_start; row < rows; row += stride) {
        const int id0 = __ldg(ids + row);
        const int id1 = __ldg(ids + row + 1);

        const float4 v0 = *reinterpret_cast<const float4*>(Wc + (size_t)id0 * D);
        const float4 v1 = *reinterpret_cast<const float4*>(Wc + (size_t)id1 * D);

        float* outp = out + (size_t)row * D + c0;

        // even row: add sin(row * f)
        float4 o0;
        o0.x = v0.x + s[0];
        o0.y = v0.y + s[1];
        o0.z = v0.z + s[2];
        o0.w = v0.w + s[3];
        *reinterpret_cast<float4*>(outp) = o0;

        // rotate +1 row
#pragma unroll
        for (int i = 0; i < VEC; i++) {
            float ns = fmaf(s[i], cd[i],  c[i] * sd[i]);
            float nc = fmaf(c[i], cd[i], -s[i] * sd[i]);
            s[i] = ns; c[i] = nc;
        }

        // odd row: add cos((row+1) * f)
        float4 o1;
        o1.x = v1.x + c[0];
        o1.y = v1.y + c[1];
        o1.z = v1.z + c[2];
        o1.w = v1.w + c[3];
        *reinterpret_cast<float4*>(outp + D) = o1;

        // jump +(stride-1) rows to this CTA's next pair
#pragma unroll
        for (int i = 0; i < VEC; i++) {
            float ns = fmaf(s[i], cj[i],  c[i] * sj[i]);
            float nc = fmaf(c[i], cj[i], -s[i] * sj[i]);
            s[i] = ns; c[i] = nc;
        }
    }
}

extern "C" void kernel_launch(void* const* d_in, const int* in_sizes, int n_in,
                              void* d_out, int out_size)
{
    const int*   ids = (const int*)d_in[0];
    const float* W   = (const float*)d_in[1];
    float*       out = (float*)d_out;

    const int rows = in_sizes[0];             // 8192 tokens
    emb_pe_kernel<<<NBLK, THREADS>>>(ids, W, out, rows);
}